// round 1
// baseline (speedup 1.0000x reference)
#include <cuda_runtime.h>
#include <math.h>

// Problem constants
#define BB  2
#define TT  2048
#define DD  2048
#define NHH 16
#define HDD 128
#define MM  (BB*TT)          // 4096 rows for dense GEMMs
#define ELEMS ((long)BB*TT*DD)   // 8388608

// GEMM tiling
#define BM 128
#define BN 128
#define BK 8
#define TM 8
#define TN 8
#define GEMM_THREADS 256

// ---------------- scratch (static device memory; no allocation) ----------------
__device__ float g_norm[ELEMS];
__device__ float g_q[ELEMS];
__device__ float g_k[ELEMS];
__device__ float g_v[ELEMS];
__device__ float g_ctx[ELEMS];
__device__ float g_h2[ELEMS];
__device__ float g_x1[ELEMS];
__device__ float g_x2[ELEMS];
__device__ float g_energy[(long)BB*NHH*TT*TT];   // 134217728 floats = 537 MB

// ---------------- block reductions ----------------
__device__ __forceinline__ float block_reduce_sum(float v) {
    __shared__ float sh[8];
    #pragma unroll
    for (int o = 16; o > 0; o >>= 1) v += __shfl_xor_sync(0xffffffffu, v, o);
    int w = threadIdx.x >> 5;
    if ((threadIdx.x & 31) == 0) sh[w] = v;
    __syncthreads();
    if (threadIdx.x < 8) {
        v = sh[threadIdx.x];
        #pragma unroll
        for (int o = 4; o > 0; o >>= 1) v += __shfl_xor_sync(0xffu, v, o);
        if (threadIdx.x == 0) sh[0] = v;
    }
    __syncthreads();
    float r = sh[0];
    __syncthreads();
    return r;
}

__device__ __forceinline__ float block_reduce_max(float v) {
    __shared__ float sh[8];
    #pragma unroll
    for (int o = 16; o > 0; o >>= 1) v = fmaxf(v, __shfl_xor_sync(0xffffffffu, v, o));
    int w = threadIdx.x >> 5;
    if ((threadIdx.x & 31) == 0) sh[w] = v;
    __syncthreads();
    if (threadIdx.x < 8) {
        v = sh[threadIdx.x];
        #pragma unroll
        for (int o = 4; o > 0; o >>= 1) v = fmaxf(v, __shfl_xor_sync(0xffu, v, o));
        if (threadIdx.x == 0) sh[0] = v;
    }
    __syncthreads();
    float r = sh[0];
    __syncthreads();
    return r;
}

// ---------------- RMSNorm: one block per row, D=2048, 256 threads, 8 elems/thread ----------------
__global__ __launch_bounds__(256) void rmsnorm_kernel(
    const float* __restrict__ x, const float* __restrict__ scale,
    float* __restrict__ y)
{
    long row = blockIdx.x;
    const float* xr = x + row * (long)DD;
    float vals[8];
    float ss = 0.f;
    #pragma unroll
    for (int i = 0; i < 8; i++) {
        int idx = threadIdx.x + i * 256;
        float v = xr[idx];
        vals[i] = v;
        ss += v * v;
    }
    ss = block_reduce_sum(ss);
    float r = rsqrtf(ss * (1.0f / DD) + 1e-5f);
    float* yr = y + row * (long)DD;
    #pragma unroll
    for (int i = 0; i < 8; i++) {
        int idx = threadIdx.x + i * 256;
        yr[idx] = scale[idx] * vals[i] * r;
    }
}

// ---------------- Softmax over last dim (row length 2048), in-place ----------------
__global__ __launch_bounds__(256) void softmax_kernel(float* __restrict__ e)
{
    float* p = e + (long)blockIdx.x * TT;
    float vals[8];
    float m = -1e30f;
    #pragma unroll
    for (int i = 0; i < 8; i++) {
        int idx = threadIdx.x + i * 256;
        vals[i] = p[idx];
        m = fmaxf(m, vals[i]);
    }
    m = block_reduce_max(m);
    float s = 0.f;
    #pragma unroll
    for (int i = 0; i < 8; i++) {
        vals[i] = expf(vals[i] - m);
        s += vals[i];
    }
    s = block_reduce_sum(s);
    float inv = 1.0f / s;
    #pragma unroll
    for (int i = 0; i < 8; i++) {
        int idx = threadIdx.x + i * 256;
        p[idx] = vals[i] * inv;
    }
}

// ---------------- SwiGLU-ish elementwise: x1 = x1*sigmoid(x1)*x2 ----------------
__global__ __launch_bounds__(256) void swiglu_kernel(
    float* __restrict__ x1, const float* __restrict__ x2, long n)
{
    long i = (long)blockIdx.x * blockDim.x + threadIdx.x;
    long stride = (long)gridDim.x * blockDim.x;
    for (; i < n; i += stride) {
        float a = x1[i];
        float sig = 1.0f / (1.0f + expf(-a));
        x1[i] = a * sig * x2[i];
    }
}

// ---------------- Tiled SGEMM, batched with (b,h) decomposition of blockIdx.z ----------------
// C = alpha * A(MxK) * op(B) [+ bias[n]] [+ resid], op(B)=B(KxN) or B(NxK)^T
template<bool TRANSB>
__global__ __launch_bounds__(GEMM_THREADS) void gemm_kernel(
    const float* __restrict__ A, const float* __restrict__ B,
    const float* __restrict__ bias, const float* __restrict__ resid,
    float* __restrict__ C,
    int M, int N, int K, int lda, int ldb, int ldc,
    long sAb, long sAh, long sBb, long sBh, long sCb, long sCh, int nh,
    float alpha)
{
    __shared__ float As[BK][BM];
    __shared__ float Bs[BK][BN];

    int z = blockIdx.z;
    int bz = z / nh, hz = z % nh;
    A += (long)bz * sAb + (long)hz * sAh;
    B += (long)bz * sBb + (long)hz * sBh;
    C += (long)bz * sCb + (long)hz * sCh;

    int bm = blockIdx.y * BM;
    int bn = blockIdx.x * BN;
    int tid = threadIdx.x;
    int tx = tid & 15;          // 0..15 (N direction)
    int ty = tid >> 4;          // 0..15 (M direction)

    // A-tile load mapping (128 rows x 8 cols): one float4 along K per thread
    int a_row = tid >> 1;
    int a_col = (tid & 1) * 4;
    // B-tile load mapping for non-transposed (8 rows x 128 cols): coalesced float4
    int b_kr = tid >> 5;
    int b_nc = (tid & 31) * 4;

    float acc[TM][TN];
    #pragma unroll
    for (int i = 0; i < TM; i++)
        #pragma unroll
        for (int j = 0; j < TN; j++) acc[i][j] = 0.f;

    for (int k0 = 0; k0 < K; k0 += BK) {
        float4 av = *reinterpret_cast<const float4*>(
            &A[(long)(bm + a_row) * lda + k0 + a_col]);
        As[a_col + 0][a_row] = av.x;
        As[a_col + 1][a_row] = av.y;
        As[a_col + 2][a_row] = av.z;
        As[a_col + 3][a_row] = av.w;

        if (TRANSB) {
            float4 bv = *reinterpret_cast<const float4*>(
                &B[(long)(bn + a_row) * ldb + k0 + a_col]);
            Bs[a_col + 0][a_row] = bv.x;
            Bs[a_col + 1][a_row] = bv.y;
            Bs[a_col + 2][a_row] = bv.z;
            Bs[a_col + 3][a_row] = bv.w;
        } else {
            float4 bv = *reinterpret_cast<const float4*>(
                &B[(long)(k0 + b_kr) * ldb + bn + b_nc]);
            *reinterpret_cast<float4*>(&Bs[b_kr][b_nc]) = bv;
        }
        __syncthreads();

        #pragma unroll
        for (int kk = 0; kk < BK; kk++) {
            float af[TM], bf[TN];
            #pragma unroll
            for (int i = 0; i < TM; i++) af[i] = As[kk][ty * TM + i];
            #pragma unroll
            for (int j = 0; j < TN; j++) bf[j] = Bs[kk][tx * TN + j];
            #pragma unroll
            for (int i = 0; i < TM; i++)
                #pragma unroll
                for (int j = 0; j < TN; j++)
                    acc[i][j] = fmaf(af[i], bf[j], acc[i][j]);
        }
        __syncthreads();
    }

    #pragma unroll
    for (int i = 0; i < TM; i++) {
        int m = bm + ty * TM + i;
        long crow = (long)m * ldc;
        #pragma unroll
        for (int j = 0; j < TN; j++) {
            int n = bn + tx * TN + j;
            float v = acc[i][j] * alpha;
            if (bias)  v += bias[n];
            if (resid) v += resid[crow + n];
            C[crow + n] = v;
        }
    }
}

// ---------------- launcher ----------------
extern "C" void kernel_launch(void* const* d_in, const int* in_sizes, int n_in,
                              void* d_out, int out_size) {
    const float* x      = (const float*)d_in[0];
    const float* Wq     = (const float*)d_in[1];
    const float* bq     = (const float*)d_in[2];
    const float* Wk     = (const float*)d_in[3];
    const float* bk     = (const float*)d_in[4];
    const float* Wv     = (const float*)d_in[5];
    const float* bv     = (const float*)d_in[6];
    const float* Wo     = (const float*)d_in[7];
    const float* bo     = (const float*)d_in[8];
    const float* scale1 = (const float*)d_in[9];
    const float* scale2 = (const float*)d_in[10];
    const float* W1     = (const float*)d_in[11];
    const float* W2     = (const float*)d_in[12];
    const float* W3     = (const float*)d_in[13];
    float* out = (float*)d_out;

    float *norm, *q, *k, *v, *ctx, *h2, *x1, *x2, *energy;
    cudaGetSymbolAddress((void**)&norm,   g_norm);
    cudaGetSymbolAddress((void**)&q,      g_q);
    cudaGetSymbolAddress((void**)&k,      g_k);
    cudaGetSymbolAddress((void**)&v,      g_v);
    cudaGetSymbolAddress((void**)&ctx,    g_ctx);
    cudaGetSymbolAddress((void**)&h2,     g_h2);
    cudaGetSymbolAddress((void**)&x1,     g_x1);
    cudaGetSymbolAddress((void**)&x2,     g_x2);
    cudaGetSymbolAddress((void**)&energy, g_energy);

    const float inv_sqrt_hd = 0.08838834764831845f; // 1/sqrt(128)

    dim3 tdim(GEMM_THREADS);
    dim3 gridDense(DD / BN, MM / BM, 1);                 // 16 x 32
    dim3 gridQK(TT / BN, TT / BM, BB * NHH);             // 16 x 16 x 32
    dim3 gridAV(HDD / BN > 0 ? HDD / BN : 1, TT / BM, BB * NHH); // 1 x 16 x 32

    // 1. h1 = rmsnorm(x, scale1)
    rmsnorm_kernel<<<MM, 256>>>(x, scale1, norm);

    // 2. q/k/v = h1 @ W{q,k,v} + b
    gemm_kernel<false><<<gridDense, tdim>>>(norm, Wq, bq, nullptr, q,
        MM, DD, DD, DD, DD, DD, 0,0,0,0,0,0, 1, 1.0f);
    gemm_kernel<false><<<gridDense, tdim>>>(norm, Wk, bk, nullptr, k,
        MM, DD, DD, DD, DD, DD, 0,0,0,0,0,0, 1, 1.0f);
    gemm_kernel<false><<<gridDense, tdim>>>(norm, Wv, bv, nullptr, v,
        MM, DD, DD, DD, DD, DD, 0,0,0,0,0,0, 1, 1.0f);

    // 3. energy[b,h] = (Q_bh @ K_bh^T) / sqrt(HD)
    gemm_kernel<true><<<gridQK, tdim>>>(q, k, nullptr, nullptr, energy,
        TT, TT, HDD, DD, DD, TT,
        (long)TT * DD, (long)HDD,          // A strides (b, h)
        (long)TT * DD, (long)HDD,          // B strides (b, h)
        (long)NHH * TT * TT, (long)TT * TT,// C strides (b, h)
        NHH, inv_sqrt_hd);

    // 4. softmax over keys, in-place
    softmax_kernel<<<BB * NHH * TT, 256>>>(energy);

    // 5. ctx[b,:,h,:] = attn_bh @ V_bh
    gemm_kernel<false><<<gridAV, tdim>>>(energy, v, nullptr, nullptr, ctx,
        TT, HDD, TT, TT, DD, DD,
        (long)NHH * TT * TT, (long)TT * TT,
        (long)TT * DD, (long)HDD,
        (long)TT * DD, (long)HDD,
        NHH, 1.0f);

    // 6. h2 = ctx @ Wo + bo + x (first residual)
    gemm_kernel<false><<<gridDense, tdim>>>(ctx, Wo, bo, x, h2,
        MM, DD, DD, DD, DD, DD, 0,0,0,0,0,0, 1, 1.0f);

    // 7. norm = rmsnorm(h2, scale2)
    rmsnorm_kernel<<<MM, 256>>>(h2, scale2, norm);

    // 8. x1 = norm @ W1
    gemm_kernel<false><<<gridDense, tdim>>>(norm, W1, nullptr, nullptr, x1,
        MM, DD, DD, DD, DD, DD, 0,0,0,0,0,0, 1, 1.0f);

    // 9. x2 = x1 @ W2   (source quirk: fc2 applied to x1)
    gemm_kernel<false><<<gridDense, tdim>>>(x1, W2, nullptr, nullptr, x2,
        MM, DD, DD, DD, DD, DD, 0,0,0,0,0,0, 1, 1.0f);

    // 10. x1 = x1 * sigmoid(x1) * x2
    swiglu_kernel<<<8192, 256>>>(x1, x2, ELEMS);

    // 11. out = x1 @ W3 + x (adds ORIGINAL input)
    gemm_kernel<false><<<gridDense, tdim>>>(x1, W3, nullptr, x, out,
        MM, DD, DD, DD, DD, DD, 0,0,0,0,0,0, 1, 1.0f);
}

// round 6
// speedup vs baseline: 1.9543x; 1.9543x over previous
#include <cuda_runtime.h>
#include <cuda_bf16.h>
#include <cstdint>
#include <math.h>

// ---------------- problem constants ----------------
#define BB  2
#define TT  2048
#define DD  2048
#define NHH 16
#define HDD 128
#define MM  (BB*TT)
#define ELEMS ((long)BB*TT*DD)

// GEMM tiling (mma.sync bf16-split)
#define GBM 128
#define GBN 128
#define GBK 32
#define GTHREADS 256

// SMEM layout (single stage, 80-byte pitch rows, 128 rows per operand half)
#define PITCH 80
#define SA_H 0
#define SA_L 10240
#define SB_H 20480
#define SB_L 30720
#define SMEM_BYTES 40960

// ---------------- scratch (static device memory) ----------------
__device__ float g_norm[ELEMS];
__device__ float g_q[ELEMS];
__device__ float g_k[ELEMS];
__device__ float g_v[ELEMS];
__device__ float g_vT[ELEMS];
__device__ float g_ctx[ELEMS];
__device__ float g_h2[ELEMS];
__device__ float g_x1[ELEMS];
__device__ float g_x2[ELEMS];
__device__ float g_wT[7L*DD*DD];
__device__ float g_energy[(long)BB*NHH*TT*TT];

// ---------------- helpers ----------------
__device__ __forceinline__ uint32_t smem_u32(const void* p) {
    uint32_t a;
    asm("{ .reg .u64 t; cvta.to.shared.u64 t, %1; cvt.u32.u64 %0, t; }" : "=r"(a) : "l"(p));
    return a;
}

__device__ __forceinline__ void ldsm4(uint32_t* r, uint32_t addr) {
    asm volatile("ldmatrix.sync.aligned.m8n8.x4.shared.b16 {%0,%1,%2,%3}, [%4];"
        : "=r"(r[0]), "=r"(r[1]), "=r"(r[2]), "=r"(r[3]) : "r"(addr));
}

__device__ __forceinline__ void mma_bf16(float* c, const uint32_t* a, const uint32_t* b) {
    asm volatile(
        "mma.sync.aligned.m16n8k16.row.col.f32.bf16.bf16.f32 "
        "{%0,%1,%2,%3}, {%4,%5,%6,%7}, {%8,%9}, {%0,%1,%2,%3};"
        : "+f"(c[0]), "+f"(c[1]), "+f"(c[2]), "+f"(c[3])
        : "r"(a[0]), "r"(a[1]), "r"(a[2]), "r"(a[3]), "r"(b[0]), "r"(b[1]));
}

// split one float4 into hi/lo bf16x4 and store (8 bytes each)
__device__ __forceinline__ void split_store(float4 v, char* hi_p, char* lo_p) {
    __nv_bfloat162 h0 = __floats2bfloat162_rn(v.x, v.y);
    __nv_bfloat162 h1 = __floats2bfloat162_rn(v.z, v.w);
    float rx = v.x - __bfloat162float(h0.x);
    float ry = v.y - __bfloat162float(h0.y);
    float rz = v.z - __bfloat162float(h1.x);
    float rw = v.w - __bfloat162float(h1.y);
    __nv_bfloat162 l0 = __floats2bfloat162_rn(rx, ry);
    __nv_bfloat162 l1 = __floats2bfloat162_rn(rz, rw);
    uint2 hv = make_uint2(*(uint32_t*)&h0, *(uint32_t*)&h1);
    uint2 lv = make_uint2(*(uint32_t*)&l0, *(uint32_t*)&l1);
    *(uint2*)hi_p = hv;
    *(uint2*)lo_p = lv;
}

// ---------------- mma.sync bf16-split GEMM ----------------
// D = alpha * A(MxK) * B(NxK)^T [+bias[n]] [+resid]; A,B fp32 K-major.
__global__ __launch_bounds__(GTHREADS) void gemm_mma(
    const float* __restrict__ A, const float* __restrict__ B,
    const float* __restrict__ bias, const float* __restrict__ resid,
    float* __restrict__ C,
    int K, int lda, int ldb, int ldc,
    long sAb, long sAh, long sBb, long sBh, long sCb, long sCh, int nh,
    float alpha)
{
    __shared__ char smem[SMEM_BYTES];
    const uint32_t sbase = smem_u32(smem);
    const int tid = threadIdx.x;
    const int wid = tid >> 5;
    const int lane = tid & 31;

    int z = blockIdx.z;
    int bz = z / nh, hz = z % nh;
    A += (long)bz * sAb + (long)hz * sAh;
    B += (long)bz * sBb + (long)hz * sBh;
    C += (long)bz * sCb + (long)hz * sCh;

    const int bm = blockIdx.y * GBM;
    const int bn = blockIdx.x * GBN;

    // warp grid: 2 (M) x 4 (N); warp tile 64x32
    const int wm = wid >> 2;
    const int wn = wid & 3;

    // ldmatrix lane addresses
    // A: lanes 0-7 rows m+0..7 chunk0 | 8-15 rows m+8..15 chunk0 | 16-23 rows m+0..7 chunk1 | 24-31 rows m+8..15 chunk1
    const uint32_t aAddr = sbase + SA_H + (uint32_t)(wm * 64 + (lane & 15)) * PITCH + (lane >> 4) * 16;
    // B: lanes 0-7 n+0..7 chunk0 | 8-15 n+0..7 chunk1 | 16-23 n+8..15 chunk0 | 24-31 n+8..15 chunk1
    const uint32_t bAddr = sbase + SB_H + (uint32_t)(wn * 32 + ((lane >> 4) << 3) + (lane & 7)) * PITCH + ((lane >> 3) & 1) * 16;

    // staging mapping: 2 threads per row, 16 floats each
    const int arow = tid >> 1;
    const int seg = tid & 1;
    const float* Agb = A + (long)(bm + arow) * lda + seg * 16;
    const float* Bgb = B + (long)(bn + arow) * ldb + seg * 16;
    char* sAhi = smem + SA_H + arow * PITCH + seg * 32;
    char* sBhi = smem + SB_H + arow * PITCH + seg * 32;

    float acc[4][4][4];
    #pragma unroll
    for (int i = 0; i < 4; i++)
        #pragma unroll
        for (int j = 0; j < 4; j++)
            #pragma unroll
            for (int r = 0; r < 4; r++) acc[i][j][r] = 0.f;

    const int NKI = K / GBK;
    float4 gA[4], gB[4];

    // prologue: load tile 0, store to smem
    #pragma unroll
    for (int j = 0; j < 4; j++) {
        gA[j] = *(const float4*)(Agb + j * 4);
        gB[j] = *(const float4*)(Bgb + j * 4);
    }
    #pragma unroll
    for (int j = 0; j < 4; j++) {
        split_store(gA[j], sAhi + j * 8, sAhi + (SA_L - SA_H) + j * 8);
        split_store(gB[j], sBhi + j * 8, sBhi + (SB_L - SB_H) + j * 8);
    }

    for (int i = 0; i < NKI; i++) {
        __syncthreads();   // stage i visible to all
        if (i + 1 < NKI) {
            long ko = (long)(i + 1) * GBK;
            #pragma unroll
            for (int j = 0; j < 4; j++) {
                gA[j] = *(const float4*)(Agb + ko + j * 4);
                gB[j] = *(const float4*)(Bgb + ko + j * 4);
            }
        }

        // compute on stage
        #pragma unroll
        for (int ks = 0; ks < 2; ks++) {
            uint32_t afh[4][4], afl[4][4];
            uint32_t bfh[2][4], bfl[2][4];
            #pragma unroll
            for (int mf = 0; mf < 4; mf++) {
                uint32_t ad = aAddr + mf * (16 * PITCH) + ks * 32;
                ldsm4(afh[mf], ad);
                ldsm4(afl[mf], ad + (SA_L - SA_H));
            }
            #pragma unroll
            for (int np = 0; np < 2; np++) {
                uint32_t bd = bAddr + np * (16 * PITCH) + ks * 32;
                ldsm4(bfh[np], bd);
                ldsm4(bfl[np], bd + (SB_L - SB_H));
            }
            #pragma unroll
            for (int mf = 0; mf < 4; mf++) {
                #pragma unroll
                for (int nf = 0; nf < 4; nf++) {
                    const int np = nf >> 1;
                    const int pr = (nf & 1) * 2;
                    mma_bf16(acc[mf][nf], afh[mf], &bfh[np][pr]);
                    mma_bf16(acc[mf][nf], afh[mf], &bfl[np][pr]);
                    mma_bf16(acc[mf][nf], afl[mf], &bfh[np][pr]);
                }
            }
        }

        __syncthreads();   // all warps done reading stage
        if (i + 1 < NKI) {
            #pragma unroll
            for (int j = 0; j < 4; j++) {
                split_store(gA[j], sAhi + j * 8, sAhi + (SA_L - SA_H) + j * 8);
                split_store(gB[j], sBhi + j * 8, sBhi + (SB_L - SB_H) + j * 8);
            }
        }
    }

    // epilogue
    const int g = lane >> 2;
    const int t = lane & 3;
    #pragma unroll
    for (int mf = 0; mf < 4; mf++) {
        #pragma unroll
        for (int nf = 0; nf < 4; nf++) {
            int row0 = bm + wm * 64 + mf * 16 + g;
            int col = bn + wn * 32 + nf * 8 + t * 2;
            float2 v0, v1;
            v0.x = acc[mf][nf][0] * alpha;
            v0.y = acc[mf][nf][1] * alpha;
            v1.x = acc[mf][nf][2] * alpha;
            v1.y = acc[mf][nf][3] * alpha;
            if (bias) {
                float2 bb = *(const float2*)(bias + col);
                v0.x += bb.x; v0.y += bb.y;
                v1.x += bb.x; v1.y += bb.y;
            }
            long o0 = (long)row0 * ldc + col;
            long o1 = (long)(row0 + 8) * ldc + col;
            if (resid) {
                float2 r0 = *(const float2*)(resid + o0);
                float2 r1 = *(const float2*)(resid + o1);
                v0.x += r0.x; v0.y += r0.y;
                v1.x += r1.x; v1.y += r1.y;
            }
            *(float2*)(C + o0) = v0;
            *(float2*)(C + o1) = v1;
        }
    }
}

// ---------------- transpose ----------------
__global__ __launch_bounds__(256) void transpose_kernel(
    const float* __restrict__ in, float* __restrict__ out,
    int ldin, int ldout, long sInB, long sInH, long sOutB, long sOutH, int nh)
{
    __shared__ float tile[32][33];
    int z = blockIdx.z, bz = z / nh, hz = z % nh;
    in  += (long)bz * sInB + (long)hz * sInH;
    out += (long)bz * sOutB + (long)hz * sOutH;
    int c0 = blockIdx.x << 5, r0 = blockIdx.y << 5;
    int tx = threadIdx.x & 31, ty = threadIdx.x >> 5;
    #pragma unroll
    for (int j = 0; j < 4; j++)
        tile[ty + j * 8][tx] = in[(long)(r0 + ty + j * 8) * ldin + c0 + tx];
    __syncthreads();
    #pragma unroll
    for (int j = 0; j < 4; j++)
        out[(long)(c0 + ty + j * 8) * ldout + r0 + tx] = tile[tx][ty + j * 8];
}

// ---------------- block reductions ----------------
__device__ __forceinline__ float block_reduce_sum(float v) {
    __shared__ float sh[8];
    #pragma unroll
    for (int o = 16; o > 0; o >>= 1) v += __shfl_xor_sync(0xffffffffu, v, o);
    int w = threadIdx.x >> 5;
    if ((threadIdx.x & 31) == 0) sh[w] = v;
    __syncthreads();
    if (threadIdx.x < 8) {
        v = sh[threadIdx.x];
        #pragma unroll
        for (int o = 4; o > 0; o >>= 1) v += __shfl_xor_sync(0xffu, v, o);
        if (threadIdx.x == 0) sh[0] = v;
    }
    __syncthreads();
    float r = sh[0];
    __syncthreads();
    return r;
}
__device__ __forceinline__ float block_reduce_max(float v) {
    __shared__ float sh[8];
    #pragma unroll
    for (int o = 16; o > 0; o >>= 1) v = fmaxf(v, __shfl_xor_sync(0xffffffffu, v, o));
    int w = threadIdx.x >> 5;
    if ((threadIdx.x & 31) == 0) sh[w] = v;
    __syncthreads();
    if (threadIdx.x < 8) {
        v = sh[threadIdx.x];
        #pragma unroll
        for (int o = 4; o > 0; o >>= 1) v = fmaxf(v, __shfl_xor_sync(0xffu, v, o));
        if (threadIdx.x == 0) sh[0] = v;
    }
    __syncthreads();
    float r = sh[0];
    __syncthreads();
    return r;
}

// ---------------- RMSNorm ----------------
__global__ __launch_bounds__(256) void rmsnorm_kernel(
    const float* __restrict__ x, const float* __restrict__ scale,
    float* __restrict__ y)
{
    long row = blockIdx.x;
    const float* xr = x + row * (long)DD;
    float vals[8];
    float ss = 0.f;
    #pragma unroll
    for (int i = 0; i < 8; i++) {
        int idx = threadIdx.x + i * 256;
        float v = xr[idx];
        vals[i] = v;
        ss += v * v;
    }
    ss = block_reduce_sum(ss);
    float r = rsqrtf(ss * (1.0f / DD) + 1e-5f);
    float* yr = y + row * (long)DD;
    #pragma unroll
    for (int i = 0; i < 8; i++) {
        int idx = threadIdx.x + i * 256;
        yr[idx] = scale[idx] * vals[i] * r;
    }
}

// ---------------- softmax ----------------
__global__ __launch_bounds__(256) void softmax_kernel(float* __restrict__ e)
{
    float* p = e + (long)blockIdx.x * TT;
    float vals[8];
    float m = -1e30f;
    #pragma unroll
    for (int i = 0; i < 8; i++) {
        int idx = threadIdx.x + i * 256;
        vals[i] = p[idx];
        m = fmaxf(m, vals[i]);
    }
    m = block_reduce_max(m);
    float s = 0.f;
    #pragma unroll
    for (int i = 0; i < 8; i++) {
        vals[i] = expf(vals[i] - m);
        s += vals[i];
    }
    s = block_reduce_sum(s);
    float inv = 1.0f / s;
    #pragma unroll
    for (int i = 0; i < 8; i++) {
        int idx = threadIdx.x + i * 256;
        p[idx] = vals[i] * inv;
    }
}

// ---------------- swiglu ----------------
__global__ __launch_bounds__(256) void swiglu_kernel(
    float* __restrict__ x1, const float* __restrict__ x2, long n)
{
    long i = (long)blockIdx.x * blockDim.x + threadIdx.x;
    long stride = (long)gridDim.x * blockDim.x;
    for (; i < n; i += stride) {
        float a = x1[i];
        float sig = 1.0f / (1.0f + expf(-a));
        x1[i] = a * sig * x2[i];
    }
}

// ---------------- launcher ----------------
extern "C" void kernel_launch(void* const* d_in, const int* in_sizes, int n_in,
                              void* d_out, int out_size) {
    const float* x      = (const float*)d_in[0];
    const float* Wq     = (const float*)d_in[1];
    const float* bq     = (const float*)d_in[2];
    const float* Wk     = (const float*)d_in[3];
    const float* bk     = (const float*)d_in[4];
    const float* Wv     = (const float*)d_in[5];
    const float* bv     = (const float*)d_in[6];
    const float* Wo     = (const float*)d_in[7];
    const float* bo     = (const float*)d_in[8];
    const float* scale1 = (const float*)d_in[9];
    const float* scale2 = (const float*)d_in[10];
    const float* W1     = (const float*)d_in[11];
    const float* W2     = (const float*)d_in[12];
    const float* W3     = (const float*)d_in[13];
    float* out = (float*)d_out;

    float *norm, *q, *k, *v, *vT, *ctx, *h2, *x1, *x2, *wT, *energy;
    cudaGetSymbolAddress((void**)&norm,   g_norm);
    cudaGetSymbolAddress((void**)&q,      g_q);
    cudaGetSymbolAddress((void**)&k,      g_k);
    cudaGetSymbolAddress((void**)&v,      g_v);
    cudaGetSymbolAddress((void**)&vT,     g_vT);
    cudaGetSymbolAddress((void**)&ctx,    g_ctx);
    cudaGetSymbolAddress((void**)&h2,     g_h2);
    cudaGetSymbolAddress((void**)&x1,     g_x1);
    cudaGetSymbolAddress((void**)&x2,     g_x2);
    cudaGetSymbolAddress((void**)&wT,     g_wT);
    cudaGetSymbolAddress((void**)&energy, g_energy);

    const float inv_sqrt_hd = 0.08838834764831845f;
    const long DSQ = (long)DD * DD;
    float* WTq = wT + 0 * DSQ;
    float* WTk = wT + 1 * DSQ;
    float* WTv = wT + 2 * DSQ;
    float* WTo = wT + 3 * DSQ;
    float* WT1 = wT + 4 * DSQ;
    float* WT2 = wT + 5 * DSQ;
    float* WT3 = wT + 6 * DSQ;

    // 0. transpose weights into [N][K] K-major form
    dim3 tgridW(DD / 32, DD / 32, 1);
    transpose_kernel<<<tgridW, 256>>>(Wq, WTq, DD, DD, 0, 0, 0, 0, 1);
    transpose_kernel<<<tgridW, 256>>>(Wk, WTk, DD, DD, 0, 0, 0, 0, 1);
    transpose_kernel<<<tgridW, 256>>>(Wv, WTv, DD, DD, 0, 0, 0, 0, 1);
    transpose_kernel<<<tgridW, 256>>>(Wo, WTo, DD, DD, 0, 0, 0, 0, 1);
    transpose_kernel<<<tgridW, 256>>>(W1, WT1, DD, DD, 0, 0, 0, 0, 1);
    transpose_kernel<<<tgridW, 256>>>(W2, WT2, DD, DD, 0, 0, 0, 0, 1);
    transpose_kernel<<<tgridW, 256>>>(W3, WT3, DD, DD, 0, 0, 0, 0, 1);

    dim3 gridDense(DD / GBN, MM / GBM, 1);       // 16 x 32
    dim3 gridQK(TT / GBN, TT / GBM, BB * NHH);   // 16 x 16 x 32
    dim3 gridAV(1, TT / GBM, BB * NHH);          // 1 x 16 x 32

    // 1. h1 = rmsnorm(x, scale1)
    rmsnorm_kernel<<<MM, 256>>>(x, scale1, norm);

    // 2. q/k/v projections
    gemm_mma<<<gridDense, GTHREADS>>>(norm, WTq, bq, nullptr, q,
        DD, DD, DD, DD, 0, 0, 0, 0, 0, 0, 1, 1.0f);
    gemm_mma<<<gridDense, GTHREADS>>>(norm, WTk, bk, nullptr, k,
        DD, DD, DD, DD, 0, 0, 0, 0, 0, 0, 1, 1.0f);
    gemm_mma<<<gridDense, GTHREADS>>>(norm, WTv, bv, nullptr, v,
        DD, DD, DD, DD, 0, 0, 0, 0, 0, 0, 1, 1.0f);

    // 3. vT[b][h][d][t] = v[b][t][h][d]
    dim3 tgridV(HDD / 32, TT / 32, BB * NHH);
    transpose_kernel<<<tgridV, 256>>>(v, vT, DD, TT,
        (long)TT * DD, (long)HDD,
        (long)NHH * HDD * TT, (long)HDD * TT, NHH);

    // 4. energy[b,h] = Q_bh @ K_bh^T / sqrt(HD)
    gemm_mma<<<gridQK, GTHREADS>>>(q, k, nullptr, nullptr, energy,
        HDD, DD, DD, TT,
        (long)TT * DD, (long)HDD,
        (long)TT * DD, (long)HDD,
        (long)NHH * TT * TT, (long)TT * TT,
        NHH, inv_sqrt_hd);

    // 5. softmax
    softmax_kernel<<<BB * NHH * TT, 256>>>(energy);

    // 6. ctx = attn @ V
    gemm_mma<<<gridAV, GTHREADS>>>(energy, vT, nullptr, nullptr, ctx,
        TT, TT, TT, DD,
        (long)NHH * TT * TT, (long)TT * TT,
        (long)NHH * HDD * TT, (long)HDD * TT,
        (long)TT * DD, (long)HDD,
        NHH, 1.0f);

    // 7. h2 = ctx @ Wo + bo + x
    gemm_mma<<<gridDense, GTHREADS>>>(ctx, WTo, bo, x, h2,
        DD, DD, DD, DD, 0, 0, 0, 0, 0, 0, 1, 1.0f);

    // 8. norm = rmsnorm(h2, scale2)
    rmsnorm_kernel<<<MM, 256>>>(h2, scale2, norm);

    // 9. x1 = norm @ W1
    gemm_mma<<<gridDense, GTHREADS>>>(norm, WT1, nullptr, nullptr, x1,
        DD, DD, DD, DD, 0, 0, 0, 0, 0, 0, 1, 1.0f);

    // 10. x2 = x1 @ W2
    gemm_mma<<<gridDense, GTHREADS>>>(x1, WT2, nullptr, nullptr, x2,
        DD, DD, DD, DD, 0, 0, 0, 0, 0, 0, 1, 1.0f);

    // 11. x1 = x1 * sigmoid(x1) * x2
    swiglu_kernel<<<8192, 256>>>(x1, x2, ELEMS);

    // 12. out = x1 @ W3 + x
    gemm_mma<<<gridDense, GTHREADS>>>(x1, WT3, nullptr, x, out,
        DD, DD, DD, DD, 0, 0, 0, 0, 0, 0, 1, 1.0f);
}

// round 7
// speedup vs baseline: 2.1581x; 1.1043x over previous
#include <cuda_runtime.h>
#include <cuda_bf16.h>
#include <cstdint>
#include <math.h>

// ---------------- problem constants ----------------
#define BB  2
#define TT  2048
#define DD  2048
#define NHH 16
#define HDD 128
#define MM  (BB*TT)
#define ELEMS ((long)BB*TT*DD)

// GEMM tiling
#define GBM 128
#define GBN 128
#define GBK 32
#define GTHREADS 256

// SMEM: per stage 4 halves (AH, AL, BH, BL), 128 rows x 80B pitch each
#define PITCH 80
#define HALF_SZ 10240
#define STG 40960
#define GEMM_SMEM (2*STG)   // 81920 bytes, double buffered

// ---------------- scratch (static device memory) ----------------
__device__ __nv_bfloat16 g_nH[ELEMS], g_nL[ELEMS];
__device__ __nv_bfloat16 g_qH[ELEMS], g_qL[ELEMS];
__device__ __nv_bfloat16 g_kH[ELEMS], g_kL[ELEMS];
__device__ float g_v[ELEMS];
__device__ __nv_bfloat16 g_vTH[ELEMS], g_vTL[ELEMS];
__device__ __nv_bfloat16 g_ctxH[ELEMS], g_ctxL[ELEMS];
__device__ float g_h2[ELEMS];
__device__ float g_x1[ELEMS], g_x2[ELEMS];
__device__ __nv_bfloat16 g_x1H[ELEMS], g_x1L[ELEMS];
__device__ __nv_bfloat16 g_gH[ELEMS], g_gL[ELEMS];
__device__ __nv_bfloat16 g_wH[7L*DD*DD], g_wL[7L*DD*DD];
__device__ float g_energy[(long)BB*NHH*TT*TT];
__device__ __nv_bfloat16 g_pH[(long)BB*NHH*TT*TT], g_pL[(long)BB*NHH*TT*TT];

// ---------------- helpers ----------------
__device__ __forceinline__ uint32_t smem_u32(const void* p) {
    uint32_t a;
    asm("{ .reg .u64 t; cvta.to.shared.u64 t, %1; cvt.u32.u64 %0, t; }" : "=r"(a) : "l"(p));
    return a;
}
__device__ __forceinline__ void ldsm4(uint32_t* r, uint32_t addr) {
    asm volatile("ldmatrix.sync.aligned.m8n8.x4.shared.b16 {%0,%1,%2,%3}, [%4];"
        : "=r"(r[0]), "=r"(r[1]), "=r"(r[2]), "=r"(r[3]) : "r"(addr));
}
__device__ __forceinline__ void mma_bf16(float* c, const uint32_t* a, const uint32_t* b) {
    asm volatile(
        "mma.sync.aligned.m16n8k16.row.col.f32.bf16.bf16.f32 "
        "{%0,%1,%2,%3}, {%4,%5,%6,%7}, {%8,%9}, {%0,%1,%2,%3};"
        : "+f"(c[0]), "+f"(c[1]), "+f"(c[2]), "+f"(c[3])
        : "r"(a[0]), "r"(a[1]), "r"(a[2]), "r"(a[3]), "r"(b[0]), "r"(b[1]));
}
__device__ __forceinline__ void cpasync16(uint32_t dst, const void* src) {
    asm volatile("cp.async.cg.shared.global [%0], [%1], 16;" :: "r"(dst), "l"(src));
}
#define CP_COMMIT() asm volatile("cp.async.commit_group;" ::: "memory")
#define CP_WAIT(N)  asm volatile("cp.async.wait_group %0;" :: "n"(N) : "memory")

__device__ __forceinline__ void split1(float v, __nv_bfloat16& h, __nv_bfloat16& l) {
    h = __float2bfloat16(v);
    l = __float2bfloat16(v - __bfloat162float(h));
}

// ---------------- bf16-split GEMM (pre-split inputs, cp.async double-buffered) ----------------
// acc = A(MxK) * B(NxK)^T with A = AH+AL, B = BH+BL (3-term). Epilogue:
//   val = alpha*acc [+bias];  if OH: write split(val);  if C: write val [+resid].
__global__ __launch_bounds__(GTHREADS) void gemm_bf16s(
    const __nv_bfloat16* __restrict__ AH, const __nv_bfloat16* __restrict__ AL,
    const __nv_bfloat16* __restrict__ BH, const __nv_bfloat16* __restrict__ BL,
    const float* __restrict__ bias, const float* __restrict__ resid,
    float* __restrict__ C, __nv_bfloat16* __restrict__ OH, __nv_bfloat16* __restrict__ OL,
    int K, int lda, int ldb, int ldc,
    long sAb, long sAh, long sBb, long sBh, long sCb, long sCh, int nh,
    float alpha)
{
    extern __shared__ char smem[];
    const uint32_t sbase = smem_u32(smem);
    const int tid = threadIdx.x;
    const int wid = tid >> 5;
    const int lane = tid & 31;

    int z = blockIdx.z;
    int bz = z / nh, hz = z % nh;
    const long aoff = (long)bz * sAb + (long)hz * sAh;
    const long boff = (long)bz * sBb + (long)hz * sBh;
    const long coff = (long)bz * sCb + (long)hz * sCh;
    AH += aoff; AL += aoff;
    BH += boff; BL += boff;

    const int bm = blockIdx.y * GBM;
    const int bn = blockIdx.x * GBN;

    // warp grid 2(M) x 4(N), warp tile 64x32
    const int wm = wid >> 2;
    const int wn = wid & 3;

    // ldmatrix lane offsets (within stage)
    const uint32_t aOff = (uint32_t)(wm * 64 + (lane & 15)) * PITCH + (lane >> 4) * 16;
    const uint32_t bOff = 2 * HALF_SZ
        + (uint32_t)(wn * 32 + ((lane >> 4) << 3) + (lane & 7)) * PITCH + ((lane >> 3) & 1) * 16;

    // copy mapping: 2048 16B-chunks/stage over 4 halves; thread does 2 chunks per half
    const int cid0 = tid * 2, cid1 = cid0 + 1;
    const int r0 = cid0 >> 2, c0 = cid0 & 3;
    const int r1 = cid1 >> 2, c1 = cid1 & 3;
    const __nv_bfloat16* aH0 = AH + (long)(bm + r0) * lda + c0 * 8;
    const __nv_bfloat16* aH1 = AH + (long)(bm + r1) * lda + c1 * 8;
    const __nv_bfloat16* aL0 = AL + (long)(bm + r0) * lda + c0 * 8;
    const __nv_bfloat16* aL1 = AL + (long)(bm + r1) * lda + c1 * 8;
    const __nv_bfloat16* bH0 = BH + (long)(bn + r0) * ldb + c0 * 8;
    const __nv_bfloat16* bH1 = BH + (long)(bn + r1) * ldb + c1 * 8;
    const __nv_bfloat16* bL0 = BL + (long)(bn + r0) * ldb + c0 * 8;
    const __nv_bfloat16* bL1 = BL + (long)(bn + r1) * ldb + c1 * 8;
    const uint32_t d0 = (uint32_t)(r0 * PITCH + c0 * 16);
    const uint32_t d1 = (uint32_t)(r1 * PITCH + c1 * 16);

    float acc[4][4][4];
    #pragma unroll
    for (int i = 0; i < 4; i++)
        #pragma unroll
        for (int j = 0; j < 4; j++)
            #pragma unroll
            for (int r = 0; r < 4; r++) acc[i][j][r] = 0.f;

    const int NKI = K / GBK;

    // prologue: stage 0
    {
        uint32_t s = sbase;
        cpasync16(s + d0,               aH0);
        cpasync16(s + d1,               aH1);
        cpasync16(s + HALF_SZ + d0,     aL0);
        cpasync16(s + HALF_SZ + d1,     aL1);
        cpasync16(s + 2*HALF_SZ + d0,   bH0);
        cpasync16(s + 2*HALF_SZ + d1,   bH1);
        cpasync16(s + 3*HALF_SZ + d0,   bL0);
        cpasync16(s + 3*HALF_SZ + d1,   bL1);
        CP_COMMIT();
    }

    for (int i = 0; i < NKI; i++) {
        const int b = i & 1;
        if (i + 1 < NKI) {
            const long ko = (long)(i + 1) * GBK;
            uint32_t s = sbase + ((i + 1) & 1) * STG;
            cpasync16(s + d0,               aH0 + ko);
            cpasync16(s + d1,               aH1 + ko);
            cpasync16(s + HALF_SZ + d0,     aL0 + ko);
            cpasync16(s + HALF_SZ + d1,     aL1 + ko);
            cpasync16(s + 2*HALF_SZ + d0,   bH0 + ko);
            cpasync16(s + 2*HALF_SZ + d1,   bH1 + ko);
            cpasync16(s + 3*HALF_SZ + d0,   bL0 + ko);
            cpasync16(s + 3*HALF_SZ + d1,   bL1 + ko);
            CP_COMMIT();
            CP_WAIT(1);
        } else {
            CP_WAIT(0);
        }
        __syncthreads();

        const uint32_t sb = sbase + b * STG;
        #pragma unroll
        for (int ks = 0; ks < 2; ks++) {
            uint32_t afh[4][4], afl[4][4];
            uint32_t bfh[2][4], bfl[2][4];
            #pragma unroll
            for (int mf = 0; mf < 4; mf++) {
                uint32_t ad = sb + aOff + mf * (16 * PITCH) + ks * 32;
                ldsm4(afh[mf], ad);
                ldsm4(afl[mf], ad + HALF_SZ);
            }
            #pragma unroll
            for (int np = 0; np < 2; np++) {
                uint32_t bd = sb + bOff + np * (16 * PITCH) + ks * 32;
                ldsm4(bfh[np], bd);
                ldsm4(bfl[np], bd + HALF_SZ);
            }
            #pragma unroll
            for (int mf = 0; mf < 4; mf++) {
                #pragma unroll
                for (int nf = 0; nf < 4; nf++) {
                    const int np = nf >> 1;
                    const int pr = (nf & 1) * 2;
                    mma_bf16(acc[mf][nf], afh[mf], &bfh[np][pr]);
                    mma_bf16(acc[mf][nf], afh[mf], &bfl[np][pr]);
                    mma_bf16(acc[mf][nf], afl[mf], &bfh[np][pr]);
                }
            }
        }
        __syncthreads();
    }

    // epilogue
    if (C) C += coff;
    if (OH) { OH += coff; OL += coff; }
    const int g = lane >> 2;
    const int t = lane & 3;
    #pragma unroll
    for (int mf = 0; mf < 4; mf++) {
        #pragma unroll
        for (int nf = 0; nf < 4; nf++) {
            int row0 = bm + wm * 64 + mf * 16 + g;
            int col = bn + wn * 32 + nf * 8 + t * 2;
            float2 v0, v1;
            v0.x = acc[mf][nf][0] * alpha;
            v0.y = acc[mf][nf][1] * alpha;
            v1.x = acc[mf][nf][2] * alpha;
            v1.y = acc[mf][nf][3] * alpha;
            if (bias) {
                float2 bb = *(const float2*)(bias + col);
                v0.x += bb.x; v0.y += bb.y;
                v1.x += bb.x; v1.y += bb.y;
            }
            long o0 = (long)row0 * ldc + col;
            long o1 = (long)(row0 + 8) * ldc + col;
            if (OH) {
                __nv_bfloat162 h0, l0, h1, l1;
                split1(v0.x, h0.x, l0.x); split1(v0.y, h0.y, l0.y);
                split1(v1.x, h1.x, l1.x); split1(v1.y, h1.y, l1.y);
                *(__nv_bfloat162*)(OH + o0) = h0;
                *(__nv_bfloat162*)(OL + o0) = l0;
                *(__nv_bfloat162*)(OH + o1) = h1;
                *(__nv_bfloat162*)(OL + o1) = l1;
            }
            if (C) {
                if (resid) {
                    float2 rr0 = *(const float2*)(resid + o0);
                    float2 rr1 = *(const float2*)(resid + o1);
                    v0.x += rr0.x; v0.y += rr0.y;
                    v1.x += rr1.x; v1.y += rr1.y;
                }
                *(float2*)(C + o0) = v0;
                *(float2*)(C + o1) = v1;
            }
        }
    }
}

// ---------------- transpose + split: out[c][r] = split(in[r][c]) ----------------
__global__ __launch_bounds__(256) void transpose_split(
    const float* __restrict__ in, __nv_bfloat16* __restrict__ oH, __nv_bfloat16* __restrict__ oL,
    int ldin, int ldout, long sInB, long sInH, long sOutB, long sOutH, int nh)
{
    __shared__ float tile[32][33];
    int z = blockIdx.z, bz = z / nh, hz = z % nh;
    in += (long)bz * sInB + (long)hz * sInH;
    long ob = (long)bz * sOutB + (long)hz * sOutH;
    oH += ob; oL += ob;
    int c0 = blockIdx.x << 5, r0 = blockIdx.y << 5;
    int tx = threadIdx.x & 31, ty = threadIdx.x >> 5;
    #pragma unroll
    for (int j = 0; j < 4; j++)
        tile[ty + j * 8][tx] = in[(long)(r0 + ty + j * 8) * ldin + c0 + tx];
    __syncthreads();
    #pragma unroll
    for (int j = 0; j < 4; j++) {
        float val = tile[tx][ty + j * 8];
        __nv_bfloat16 h, l;
        split1(val, h, l);
        long o = (long)(c0 + ty + j * 8) * ldout + r0 + tx;
        oH[o] = h; oL[o] = l;
    }
}

// ---------------- block reductions ----------------
__device__ __forceinline__ float block_reduce_sum(float v) {
    __shared__ float sh[8];
    #pragma unroll
    for (int o = 16; o > 0; o >>= 1) v += __shfl_xor_sync(0xffffffffu, v, o);
    int w = threadIdx.x >> 5;
    if ((threadIdx.x & 31) == 0) sh[w] = v;
    __syncthreads();
    if (threadIdx.x < 8) {
        v = sh[threadIdx.x];
        #pragma unroll
        for (int o = 4; o > 0; o >>= 1) v += __shfl_xor_sync(0xffu, v, o);
        if (threadIdx.x == 0) sh[0] = v;
    }
    __syncthreads();
    float r = sh[0];
    __syncthreads();
    return r;
}
__device__ __forceinline__ float block_reduce_max(float v) {
    __shared__ float sh[8];
    #pragma unroll
    for (int o = 16; o > 0; o >>= 1) v = fmaxf(v, __shfl_xor_sync(0xffffffffu, v, o));
    int w = threadIdx.x >> 5;
    if ((threadIdx.x & 31) == 0) sh[w] = v;
    __syncthreads();
    if (threadIdx.x < 8) {
        v = sh[threadIdx.x];
        #pragma unroll
        for (int o = 4; o > 0; o >>= 1) v = fmaxf(v, __shfl_xor_sync(0xffu, v, o));
        if (threadIdx.x == 0) sh[0] = v;
    }
    __syncthreads();
    float r = sh[0];
    __syncthreads();
    return r;
}

// ---------------- RMSNorm -> split bf16 ----------------
__global__ __launch_bounds__(256) void rmsnorm_split(
    const float* __restrict__ x, const float* __restrict__ scale,
    __nv_bfloat16* __restrict__ yH, __nv_bfloat16* __restrict__ yL)
{
    long row = blockIdx.x;
    const float* xr = x + row * (long)DD;
    float vals[8];
    float ss = 0.f;
    #pragma unroll
    for (int i = 0; i < 8; i++) {
        int idx = threadIdx.x + i * 256;
        float v = xr[idx];
        vals[i] = v;
        ss += v * v;
    }
    ss = block_reduce_sum(ss);
    float r = rsqrtf(ss * (1.0f / DD) + 1e-5f);
    long base = row * (long)DD;
    #pragma unroll
    for (int i = 0; i < 8; i++) {
        int idx = threadIdx.x + i * 256;
        float v = scale[idx] * vals[i] * r;
        __nv_bfloat16 h, l;
        split1(v, h, l);
        yH[base + idx] = h; yL[base + idx] = l;
    }
}

// ---------------- softmax -> split bf16 probs ----------------
__global__ __launch_bounds__(256) void softmax_split(
    const float* __restrict__ e,
    __nv_bfloat16* __restrict__ pH, __nv_bfloat16* __restrict__ pL)
{
    long base = (long)blockIdx.x * TT;
    const float* p = e + base;
    float vals[8];
    float m = -1e30f;
    #pragma unroll
    for (int i = 0; i < 8; i++) {
        int idx = threadIdx.x + i * 256;
        vals[i] = p[idx];
        m = fmaxf(m, vals[i]);
    }
    m = block_reduce_max(m);
    float s = 0.f;
    #pragma unroll
    for (int i = 0; i < 8; i++) {
        vals[i] = expf(vals[i] - m);
        s += vals[i];
    }
    s = block_reduce_sum(s);
    float inv = 1.0f / s;
    #pragma unroll
    for (int i = 0; i < 8; i++) {
        int idx = threadIdx.x + i * 256;
        float v = vals[i] * inv;
        __nv_bfloat16 h, l;
        split1(v, h, l);
        pH[base + idx] = h; pL[base + idx] = l;
    }
}

// ---------------- swiglu -> split bf16 ----------------
__global__ __launch_bounds__(256) void swiglu_split(
    const float* __restrict__ x1, const float* __restrict__ x2,
    __nv_bfloat16* __restrict__ gH, __nv_bfloat16* __restrict__ gL, long n)
{
    long i = (long)blockIdx.x * blockDim.x + threadIdx.x;
    long stride = (long)gridDim.x * blockDim.x;
    for (; i < n; i += stride) {
        float a = x1[i];
        float sig = 1.0f / (1.0f + expf(-a));
        float v = a * sig * x2[i];
        __nv_bfloat16 h, l;
        split1(v, h, l);
        gH[i] = h; gL[i] = l;
    }
}

// ---------------- launcher ----------------
extern "C" void kernel_launch(void* const* d_in, const int* in_sizes, int n_in,
                              void* d_out, int out_size) {
    const float* x      = (const float*)d_in[0];
    const float* Wq     = (const float*)d_in[1];
    const float* bq     = (const float*)d_in[2];
    const float* Wk     = (const float*)d_in[3];
    const float* bk     = (const float*)d_in[4];
    const float* Wv     = (const float*)d_in[5];
    const float* bv     = (const float*)d_in[6];
    const float* Wo     = (const float*)d_in[7];
    const float* bo     = (const float*)d_in[8];
    const float* scale1 = (const float*)d_in[9];
    const float* scale2 = (const float*)d_in[10];
    const float* W1     = (const float*)d_in[11];
    const float* W2     = (const float*)d_in[12];
    const float* W3     = (const float*)d_in[13];
    float* out = (float*)d_out;

    __nv_bfloat16 *nH, *nL, *qH, *qL, *kH, *kL, *vTH, *vTL, *ctxH, *ctxL;
    __nv_bfloat16 *x1H, *x1L, *gH, *gL, *wH, *wL, *pH, *pL;
    float *v, *h2, *x1, *x2, *energy;
    cudaGetSymbolAddress((void**)&nH, g_nH);     cudaGetSymbolAddress((void**)&nL, g_nL);
    cudaGetSymbolAddress((void**)&qH, g_qH);     cudaGetSymbolAddress((void**)&qL, g_qL);
    cudaGetSymbolAddress((void**)&kH, g_kH);     cudaGetSymbolAddress((void**)&kL, g_kL);
    cudaGetSymbolAddress((void**)&v, g_v);
    cudaGetSymbolAddress((void**)&vTH, g_vTH);   cudaGetSymbolAddress((void**)&vTL, g_vTL);
    cudaGetSymbolAddress((void**)&ctxH, g_ctxH); cudaGetSymbolAddress((void**)&ctxL, g_ctxL);
    cudaGetSymbolAddress((void**)&h2, g_h2);
    cudaGetSymbolAddress((void**)&x1, g_x1);     cudaGetSymbolAddress((void**)&x2, g_x2);
    cudaGetSymbolAddress((void**)&x1H, g_x1H);   cudaGetSymbolAddress((void**)&x1L, g_x1L);
    cudaGetSymbolAddress((void**)&gH, g_gH);     cudaGetSymbolAddress((void**)&gL, g_gL);
    cudaGetSymbolAddress((void**)&wH, g_wH);     cudaGetSymbolAddress((void**)&wL, g_wL);
    cudaGetSymbolAddress((void**)&pH, g_pH);     cudaGetSymbolAddress((void**)&pL, g_pL);
    cudaGetSymbolAddress((void**)&energy, g_energy);

    cudaFuncSetAttribute(gemm_bf16s, cudaFuncAttributeMaxDynamicSharedMemorySize, GEMM_SMEM);

    const float inv_sqrt_hd = 0.08838834764831845f;
    const long DSQ = (long)DD * DD;
    __nv_bfloat16 *WqH = wH + 0*DSQ, *WqL = wL + 0*DSQ;
    __nv_bfloat16 *WkH = wH + 1*DSQ, *WkL = wL + 1*DSQ;
    __nv_bfloat16 *WvH = wH + 2*DSQ, *WvL = wL + 2*DSQ;
    __nv_bfloat16 *WoH = wH + 3*DSQ, *WoL = wL + 3*DSQ;
    __nv_bfloat16 *W1H = wH + 4*DSQ, *W1L = wL + 4*DSQ;
    __nv_bfloat16 *W2H = wH + 5*DSQ, *W2L = wL + 5*DSQ;
    __nv_bfloat16 *W3H = wH + 6*DSQ, *W3L = wL + 6*DSQ;

    // 0. transpose + split weights to [N][K] bf16 hi/lo
    dim3 tgridW(DD / 32, DD / 32, 1);
    transpose_split<<<tgridW, 256>>>(Wq, WqH, WqL, DD, DD, 0, 0, 0, 0, 1);
    transpose_split<<<tgridW, 256>>>(Wk, WkH, WkL, DD, DD, 0, 0, 0, 0, 1);
    transpose_split<<<tgridW, 256>>>(Wv, WvH, WvL, DD, DD, 0, 0, 0, 0, 1);
    transpose_split<<<tgridW, 256>>>(Wo, WoH, WoL, DD, DD, 0, 0, 0, 0, 1);
    transpose_split<<<tgridW, 256>>>(W1, W1H, W1L, DD, DD, 0, 0, 0, 0, 1);
    transpose_split<<<tgridW, 256>>>(W2, W2H, W2L, DD, DD, 0, 0, 0, 0, 1);
    transpose_split<<<tgridW, 256>>>(W3, W3H, W3L, DD, DD, 0, 0, 0, 0, 1);

    dim3 gridDense(DD / GBN, MM / GBM, 1);       // 16 x 32
    dim3 gridQK(TT / GBN, TT / GBM, BB * NHH);   // 16 x 16 x 32
    dim3 gridAV(1, TT / GBM, BB * NHH);          // 1 x 16 x 32

    // 1. norm1
    rmsnorm_split<<<MM, 256>>>(x, scale1, nH, nL);

    // 2. q/k/v projections
    gemm_bf16s<<<gridDense, GTHREADS, GEMM_SMEM>>>(nH, nL, WqH, WqL, bq, nullptr,
        nullptr, qH, qL, DD, DD, DD, DD, 0,0,0,0,0,0, 1, 1.0f);
    gemm_bf16s<<<gridDense, GTHREADS, GEMM_SMEM>>>(nH, nL, WkH, WkL, bk, nullptr,
        nullptr, kH, kL, DD, DD, DD, DD, 0,0,0,0,0,0, 1, 1.0f);
    gemm_bf16s<<<gridDense, GTHREADS, GEMM_SMEM>>>(nH, nL, WvH, WvL, bv, nullptr,
        v, nullptr, nullptr, DD, DD, DD, DD, 0,0,0,0,0,0, 1, 1.0f);

    // 3. vT split: [b,h,d,t]
    dim3 tgridV(HDD / 32, TT / 32, BB * NHH);
    transpose_split<<<tgridV, 256>>>(v, vTH, vTL, DD, TT,
        (long)TT * DD, (long)HDD,
        (long)NHH * HDD * TT, (long)HDD * TT, NHH);

    // 4. energy = Q K^T / sqrt(HD)
    gemm_bf16s<<<gridQK, GTHREADS, GEMM_SMEM>>>(qH, qL, kH, kL, nullptr, nullptr,
        energy, nullptr, nullptr,
        HDD, DD, DD, TT,
        (long)TT * DD, (long)HDD,
        (long)TT * DD, (long)HDD,
        (long)NHH * TT * TT, (long)TT * TT,
        NHH, inv_sqrt_hd);

    // 5. softmax -> split probs
    softmax_split<<<BB * NHH * TT, 256>>>(energy, pH, pL);

    // 6. ctx = P @ V  (split output only)
    gemm_bf16s<<<gridAV, GTHREADS, GEMM_SMEM>>>(pH, pL, vTH, vTL, nullptr, nullptr,
        nullptr, ctxH, ctxL,
        TT, TT, TT, DD,
        (long)NHH * TT * TT, (long)TT * TT,
        (long)NHH * HDD * TT, (long)HDD * TT,
        (long)TT * DD, (long)HDD,
        NHH, 1.0f);

    // 7. h2 = ctx @ Wo + bo + x
    gemm_bf16s<<<gridDense, GTHREADS, GEMM_SMEM>>>(ctxH, ctxL, WoH, WoL, bo, x,
        h2, nullptr, nullptr, DD, DD, DD, DD, 0,0,0,0,0,0, 1, 1.0f);

    // 8. norm2
    rmsnorm_split<<<MM, 256>>>(h2, scale2, nH, nL);

    // 9. x1 = norm @ W1  (fp32 + split)
    gemm_bf16s<<<gridDense, GTHREADS, GEMM_SMEM>>>(nH, nL, W1H, W1L, nullptr, nullptr,
        x1, x1H, x1L, DD, DD, DD, DD, 0,0,0,0,0,0, 1, 1.0f);

    // 10. x2 = x1 @ W2
    gemm_bf16s<<<gridDense, GTHREADS, GEMM_SMEM>>>(x1H, x1L, W2H, W2L, nullptr, nullptr,
        x2, nullptr, nullptr, DD, DD, DD, DD, 0,0,0,0,0,0, 1, 1.0f);

    // 11. g = x1*sigmoid(x1)*x2 -> split
    swiglu_split<<<8192, 256>>>(x1, x2, gH, gL, ELEMS);

    // 12. out = g @ W3 + x
    gemm_bf16s<<<gridDense, GTHREADS, GEMM_SMEM>>>(gH, gL, W3H, W3L, nullptr, x,
        out, nullptr, nullptr, DD, DD, DD, DD, 0,0,0,0,0,0, 1, 1.0f);
}

// round 8
// speedup vs baseline: 2.2049x; 1.0217x over previous
#include <cuda_runtime.h>
#include <cuda_bf16.h>
#include <cstdint>
#include <math.h>

// ---------------- problem constants ----------------
#define BB  2
#define TT  2048
#define DD  2048
#define NHH 16
#define HDD 128
#define MM  (BB*TT)
#define ELEMS ((long)BB*TT*DD)

// GEMM tiling
#define GBM 128
#define GBN 128
#define GBK 32
#define GTHREADS 256

// SMEM: per stage 4 halves (AH, AL, BH, BL), 128 rows x 80B pitch each
#define PITCH 80
#define HALF_SZ 10240
#define STG 40960
#define NSTAGE 4
#define GEMM_SMEM (NSTAGE*STG)   // 163840 bytes

// epilogue modes (bitmask)
#define EPI_C      1   // write fp32 C (+resid)
#define EPI_SPLIT  2   // write split bf16 OH/OL of val
#define EPI_SWIGLU 4   // val = resid*sigmoid(resid)*val, then split write

// ---------------- scratch (static device memory) ----------------
__device__ __nv_bfloat16 g_nH[ELEMS], g_nL[ELEMS];
__device__ __nv_bfloat16 g_qH[ELEMS], g_qL[ELEMS];
__device__ __nv_bfloat16 g_kH[ELEMS], g_kL[ELEMS];
__device__ float g_v[ELEMS];
__device__ __nv_bfloat16 g_vTH[ELEMS], g_vTL[ELEMS];
__device__ __nv_bfloat16 g_ctxH[ELEMS], g_ctxL[ELEMS];
__device__ float g_h2[ELEMS];
__device__ float g_x1[ELEMS];
__device__ __nv_bfloat16 g_x1H[ELEMS], g_x1L[ELEMS];
__device__ __nv_bfloat16 g_gH[ELEMS], g_gL[ELEMS];
__device__ __nv_bfloat16 g_wH[7L*DD*DD], g_wL[7L*DD*DD];
__device__ float g_energy[(long)BB*NHH*TT*TT];
__device__ __nv_bfloat16 g_pH[(long)BB*NHH*TT*TT], g_pL[(long)BB*NHH*TT*TT];

// ---------------- helpers ----------------
__device__ __forceinline__ uint32_t smem_u32(const void* p) {
    uint32_t a;
    asm("{ .reg .u64 t; cvta.to.shared.u64 t, %1; cvt.u32.u64 %0, t; }" : "=r"(a) : "l"(p));
    return a;
}
__device__ __forceinline__ void ldsm4(uint32_t* r, uint32_t addr) {
    asm volatile("ldmatrix.sync.aligned.m8n8.x4.shared.b16 {%0,%1,%2,%3}, [%4];"
        : "=r"(r[0]), "=r"(r[1]), "=r"(r[2]), "=r"(r[3]) : "r"(addr));
}
__device__ __forceinline__ void mma_bf16(float* c, const uint32_t* a, const uint32_t* b) {
    asm volatile(
        "mma.sync.aligned.m16n8k16.row.col.f32.bf16.bf16.f32 "
        "{%0,%1,%2,%3}, {%4,%5,%6,%7}, {%8,%9}, {%0,%1,%2,%3};"
        : "+f"(c[0]), "+f"(c[1]), "+f"(c[2]), "+f"(c[3])
        : "r"(a[0]), "r"(a[1]), "r"(a[2]), "r"(a[3]), "r"(b[0]), "r"(b[1]));
}
__device__ __forceinline__ void cpasync16(uint32_t dst, const void* src) {
    asm volatile("cp.async.cg.shared.global [%0], [%1], 16;" :: "r"(dst), "l"(src));
}
#define CP_COMMIT() asm volatile("cp.async.commit_group;" ::: "memory")
#define CP_WAIT(N)  asm volatile("cp.async.wait_group %0;" :: "n"(N) : "memory")

__device__ __forceinline__ void split1(float v, __nv_bfloat16& h, __nv_bfloat16& l) {
    h = __float2bfloat16(v);
    l = __float2bfloat16(v - __bfloat162float(h));
}

// ---------------- bf16-split GEMM (4-stage cp.async pipeline, 1 barrier/iter) ----------------
__global__ __launch_bounds__(GTHREADS) void gemm_bf16s(
    const __nv_bfloat16* __restrict__ AH, const __nv_bfloat16* __restrict__ AL,
    const __nv_bfloat16* __restrict__ BH, const __nv_bfloat16* __restrict__ BL,
    const float* __restrict__ bias, const float* __restrict__ resid,
    float* __restrict__ C, __nv_bfloat16* __restrict__ OH, __nv_bfloat16* __restrict__ OL,
    int K, int lda, int ldb, int ldc,
    long sAb, long sAh, long sBb, long sBh, long sCb, long sCh, int nh,
    float alpha, int mode)
{
    extern __shared__ char smem[];
    const uint32_t sbase = smem_u32(smem);
    const int tid = threadIdx.x;
    const int wid = tid >> 5;
    const int lane = tid & 31;

    int z = blockIdx.z;
    int bz = z / nh, hz = z % nh;
    const long aoff = (long)bz * sAb + (long)hz * sAh;
    const long boff = (long)bz * sBb + (long)hz * sBh;
    const long coff = (long)bz * sCb + (long)hz * sCh;
    AH += aoff; AL += aoff;
    BH += boff; BL += boff;

    const int bm = blockIdx.y * GBM;
    const int bn = blockIdx.x * GBN;

    // warp grid 2(M) x 4(N), warp tile 64x32
    const int wm = wid >> 2;
    const int wn = wid & 3;

    // ldmatrix lane offsets (within stage)
    const uint32_t aOff = (uint32_t)(wm * 64 + (lane & 15)) * PITCH + (lane >> 4) * 16;
    const uint32_t bOff = 2 * HALF_SZ
        + (uint32_t)(wn * 32 + ((lane >> 4) << 3) + (lane & 7)) * PITCH + ((lane >> 3) & 1) * 16;

    // copy mapping: 512 16B-chunks per half; thread does 2 chunks per half
    const int cid0 = tid * 2, cid1 = cid0 + 1;
    const int r0 = cid0 >> 2, c0 = cid0 & 3;
    const int r1 = cid1 >> 2, c1 = cid1 & 3;
    const __nv_bfloat16* aH0 = AH + (long)(bm + r0) * lda + c0 * 8;
    const __nv_bfloat16* aH1 = AH + (long)(bm + r1) * lda + c1 * 8;
    const __nv_bfloat16* aL0 = AL + (long)(bm + r0) * lda + c0 * 8;
    const __nv_bfloat16* aL1 = AL + (long)(bm + r1) * lda + c1 * 8;
    const __nv_bfloat16* bH0 = BH + (long)(bn + r0) * ldb + c0 * 8;
    const __nv_bfloat16* bH1 = BH + (long)(bn + r1) * ldb + c1 * 8;
    const __nv_bfloat16* bL0 = BL + (long)(bn + r0) * ldb + c0 * 8;
    const __nv_bfloat16* bL1 = BL + (long)(bn + r1) * ldb + c1 * 8;
    const uint32_t d0 = (uint32_t)(r0 * PITCH + c0 * 16);
    const uint32_t d1 = (uint32_t)(r1 * PITCH + c1 * 16);

#define ISSUE_STAGE(SIDX, KO) do {                                   \
        uint32_t s_ = sbase + (uint32_t)(SIDX) * STG;                \
        long ko_ = (KO);                                             \
        cpasync16(s_ + d0,             aH0 + ko_);                   \
        cpasync16(s_ + d1,             aH1 + ko_);                   \
        cpasync16(s_ + HALF_SZ + d0,   aL0 + ko_);                   \
        cpasync16(s_ + HALF_SZ + d1,   aL1 + ko_);                   \
        cpasync16(s_ + 2*HALF_SZ + d0, bH0 + ko_);                   \
        cpasync16(s_ + 2*HALF_SZ + d1, bH1 + ko_);                   \
        cpasync16(s_ + 3*HALF_SZ + d0, bL0 + ko_);                   \
        cpasync16(s_ + 3*HALF_SZ + d1, bL1 + ko_);                   \
    } while (0)

    float acc[4][4][4];
    #pragma unroll
    for (int i = 0; i < 4; i++)
        #pragma unroll
        for (int j = 0; j < 4; j++)
            #pragma unroll
            for (int r = 0; r < 4; r++) acc[i][j][r] = 0.f;

    const int NKI = K / GBK;

    // prologue: issue stages 0..2 (one commit group per stage, unconditionally)
    #pragma unroll
    for (int s = 0; s < NSTAGE - 1; s++) {
        if (s < NKI) ISSUE_STAGE(s, (long)s * GBK);
        CP_COMMIT();
    }

    for (int i = 0; i < NKI; i++) {
        CP_WAIT(2);          // stage i arrived (3 groups max in flight)
        __syncthreads();     // also: all warps done computing stage i-1 -> buffer (i+3)%4 free

        if (i + 3 < NKI) ISSUE_STAGE((i + 3) & (NSTAGE - 1), (long)(i + 3) * GBK);
        CP_COMMIT();

        const uint32_t sb = sbase + (uint32_t)(i & (NSTAGE - 1)) * STG;
        #pragma unroll
        for (int ks = 0; ks < 2; ks++) {
            uint32_t afh[4][4], afl[4][4];
            uint32_t bfh[2][4], bfl[2][4];
            #pragma unroll
            for (int mf = 0; mf < 4; mf++) {
                uint32_t ad = sb + aOff + mf * (16 * PITCH) + ks * 32;
                ldsm4(afh[mf], ad);
                ldsm4(afl[mf], ad + HALF_SZ);
            }
            #pragma unroll
            for (int np = 0; np < 2; np++) {
                uint32_t bd = sb + bOff + np * (16 * PITCH) + ks * 32;
                ldsm4(bfh[np], bd);
                ldsm4(bfl[np], bd + HALF_SZ);
            }
            #pragma unroll
            for (int mf = 0; mf < 4; mf++) {
                #pragma unroll
                for (int nf = 0; nf < 4; nf++) {
                    const int np = nf >> 1;
                    const int pr = (nf & 1) * 2;
                    mma_bf16(acc[mf][nf], afh[mf], &bfh[np][pr]);
                    mma_bf16(acc[mf][nf], afh[mf], &bfl[np][pr]);
                    mma_bf16(acc[mf][nf], afl[mf], &bfh[np][pr]);
                }
            }
        }
    }
#undef ISSUE_STAGE

    // epilogue
    float* Cp = C ? C + coff : nullptr;
    __nv_bfloat16* OHp = OH ? OH + coff : nullptr;
    __nv_bfloat16* OLp = OL ? OL + coff : nullptr;
    const int g = lane >> 2;
    const int t = lane & 3;
    #pragma unroll
    for (int mf = 0; mf < 4; mf++) {
        #pragma unroll
        for (int nf = 0; nf < 4; nf++) {
            int row0 = bm + wm * 64 + mf * 16 + g;
            int col = bn + wn * 32 + nf * 8 + t * 2;
            float2 v0, v1;
            v0.x = acc[mf][nf][0] * alpha;
            v0.y = acc[mf][nf][1] * alpha;
            v1.x = acc[mf][nf][2] * alpha;
            v1.y = acc[mf][nf][3] * alpha;
            if (bias) {
                float2 bb = *(const float2*)(bias + col);
                v0.x += bb.x; v0.y += bb.y;
                v1.x += bb.x; v1.y += bb.y;
            }
            long o0 = (long)row0 * ldc + col;
            long o1 = (long)(row0 + 8) * ldc + col;
            if (mode & EPI_SWIGLU) {
                // val = x2; rr = x1; g = x1*sigmoid(x1)*x2
                float2 rr0 = *(const float2*)(resid + o0);
                float2 rr1 = *(const float2*)(resid + o1);
                v0.x = rr0.x * (1.0f / (1.0f + expf(-rr0.x))) * v0.x;
                v0.y = rr0.y * (1.0f / (1.0f + expf(-rr0.y))) * v0.y;
                v1.x = rr1.x * (1.0f / (1.0f + expf(-rr1.x))) * v1.x;
                v1.y = rr1.y * (1.0f / (1.0f + expf(-rr1.y))) * v1.y;
            }
            if (mode & EPI_SPLIT) {
                __nv_bfloat162 h0, l0, h1, l1;
                split1(v0.x, h0.x, l0.x); split1(v0.y, h0.y, l0.y);
                split1(v1.x, h1.x, l1.x); split1(v1.y, h1.y, l1.y);
                *(__nv_bfloat162*)(OHp + o0) = h0;
                *(__nv_bfloat162*)(OLp + o0) = l0;
                *(__nv_bfloat162*)(OHp + o1) = h1;
                *(__nv_bfloat162*)(OLp + o1) = l1;
            }
            if (mode & EPI_C) {
                if (resid) {
                    float2 rr0 = *(const float2*)(resid + o0);
                    float2 rr1 = *(const float2*)(resid + o1);
                    v0.x += rr0.x; v0.y += rr0.y;
                    v1.x += rr1.x; v1.y += rr1.y;
                }
                *(float2*)(Cp + o0) = v0;
                *(float2*)(Cp + o1) = v1;
            }
        }
    }
}

// ---------------- transpose + split ----------------
__global__ __launch_bounds__(256) void transpose_split(
    const float* __restrict__ in, __nv_bfloat16* __restrict__ oH, __nv_bfloat16* __restrict__ oL,
    int ldin, int ldout, long sInB, long sInH, long sOutB, long sOutH, int nh)
{
    __shared__ float tile[32][33];
    int z = blockIdx.z, bz = z / nh, hz = z % nh;
    in += (long)bz * sInB + (long)hz * sInH;
    long ob = (long)bz * sOutB + (long)hz * sOutH;
    oH += ob; oL += ob;
    int c0 = blockIdx.x << 5, r0 = blockIdx.y << 5;
    int tx = threadIdx.x & 31, ty = threadIdx.x >> 5;
    #pragma unroll
    for (int j = 0; j < 4; j++)
        tile[ty + j * 8][tx] = in[(long)(r0 + ty + j * 8) * ldin + c0 + tx];
    __syncthreads();
    #pragma unroll
    for (int j = 0; j < 4; j++) {
        float val = tile[tx][ty + j * 8];
        __nv_bfloat16 h, l;
        split1(val, h, l);
        long o = (long)(c0 + ty + j * 8) * ldout + r0 + tx;
        oH[o] = h; oL[o] = l;
    }
}

// ---------------- block reductions ----------------
__device__ __forceinline__ float block_reduce_sum(float v) {
    __shared__ float sh[8];
    #pragma unroll
    for (int o = 16; o > 0; o >>= 1) v += __shfl_xor_sync(0xffffffffu, v, o);
    int w = threadIdx.x >> 5;
    if ((threadIdx.x & 31) == 0) sh[w] = v;
    __syncthreads();
    if (threadIdx.x < 8) {
        v = sh[threadIdx.x];
        #pragma unroll
        for (int o = 4; o > 0; o >>= 1) v += __shfl_xor_sync(0xffu, v, o);
        if (threadIdx.x == 0) sh[0] = v;
    }
    __syncthreads();
    float r = sh[0];
    __syncthreads();
    return r;
}
__device__ __forceinline__ float block_reduce_max(float v) {
    __shared__ float sh[8];
    #pragma unroll
    for (int o = 16; o > 0; o >>= 1) v = fmaxf(v, __shfl_xor_sync(0xffffffffu, v, o));
    int w = threadIdx.x >> 5;
    if ((threadIdx.x & 31) == 0) sh[w] = v;
    __syncthreads();
    if (threadIdx.x < 8) {
        v = sh[threadIdx.x];
        #pragma unroll
        for (int o = 4; o > 0; o >>= 1) v = fmaxf(v, __shfl_xor_sync(0xffu, v, o));
        if (threadIdx.x == 0) sh[0] = v;
    }
    __syncthreads();
    float r = sh[0];
    __syncthreads();
    return r;
}

// ---------------- RMSNorm -> split bf16 ----------------
__global__ __launch_bounds__(256) void rmsnorm_split(
    const float* __restrict__ x, const float* __restrict__ scale,
    __nv_bfloat16* __restrict__ yH, __nv_bfloat16* __restrict__ yL)
{
    long row = blockIdx.x;
    const float* xr = x + row * (long)DD;
    float vals[8];
    float ss = 0.f;
    #pragma unroll
    for (int i = 0; i < 8; i++) {
        int idx = threadIdx.x + i * 256;
        float v = xr[idx];
        vals[i] = v;
        ss += v * v;
    }
    ss = block_reduce_sum(ss);
    float r = rsqrtf(ss * (1.0f / DD) + 1e-5f);
    long base = row * (long)DD;
    #pragma unroll
    for (int i = 0; i < 8; i++) {
        int idx = threadIdx.x + i * 256;
        float v = scale[idx] * vals[i] * r;
        __nv_bfloat16 h, l;
        split1(v, h, l);
        yH[base + idx] = h; yL[base + idx] = l;
    }
}

// ---------------- softmax -> split bf16 probs (vectorized) ----------------
__global__ __launch_bounds__(256) void softmax_split(
    const float* __restrict__ e,
    __nv_bfloat16* __restrict__ pH, __nv_bfloat16* __restrict__ pL)
{
    long base = (long)blockIdx.x * TT;
    const float4* p4 = (const float4*)(e + base);
    float4 vals[2];
    float m = -1e30f;
    #pragma unroll
    for (int i = 0; i < 2; i++) {
        vals[i] = p4[threadIdx.x + i * 256];
        m = fmaxf(m, fmaxf(fmaxf(vals[i].x, vals[i].y), fmaxf(vals[i].z, vals[i].w)));
    }
    m = block_reduce_max(m);
    float s = 0.f;
    #pragma unroll
    for (int i = 0; i < 2; i++) {
        vals[i].x = expf(vals[i].x - m);
        vals[i].y = expf(vals[i].y - m);
        vals[i].z = expf(vals[i].z - m);
        vals[i].w = expf(vals[i].w - m);
        s += vals[i].x + vals[i].y + vals[i].z + vals[i].w;
    }
    s = block_reduce_sum(s);
    float inv = 1.0f / s;
    #pragma unroll
    for (int i = 0; i < 2; i++) {
        long o = base + (threadIdx.x + i * 256) * 4;
        __nv_bfloat162 h0, l0, h1, l1;
        split1(vals[i].x * inv, h0.x, l0.x);
        split1(vals[i].y * inv, h0.y, l0.y);
        split1(vals[i].z * inv, h1.x, l1.x);
        split1(vals[i].w * inv, h1.y, l1.y);
        *(__nv_bfloat162*)(pH + o) = h0;
        *(__nv_bfloat162*)(pH + o + 2) = h1;
        *(__nv_bfloat162*)(pL + o) = l0;
        *(__nv_bfloat162*)(pL + o + 2) = l1;
    }
}

// ---------------- launcher ----------------
extern "C" void kernel_launch(void* const* d_in, const int* in_sizes, int n_in,
                              void* d_out, int out_size) {
    const float* x      = (const float*)d_in[0];
    const float* Wq     = (const float*)d_in[1];
    const float* bq     = (const float*)d_in[2];
    const float* Wk     = (const float*)d_in[3];
    const float* bk     = (const float*)d_in[4];
    const float* Wv     = (const float*)d_in[5];
    const float* bv     = (const float*)d_in[6];
    const float* Wo     = (const float*)d_in[7];
    const float* bo     = (const float*)d_in[8];
    const float* scale1 = (const float*)d_in[9];
    const float* scale2 = (const float*)d_in[10];
    const float* W1     = (const float*)d_in[11];
    const float* W2     = (const float*)d_in[12];
    const float* W3     = (const float*)d_in[13];
    float* out = (float*)d_out;

    __nv_bfloat16 *nH, *nL, *qH, *qL, *kH, *kL, *vTH, *vTL, *ctxH, *ctxL;
    __nv_bfloat16 *x1H, *x1L, *gH, *gL, *wH, *wL, *pH, *pL;
    float *v, *h2, *x1, *energy;
    cudaGetSymbolAddress((void**)&nH, g_nH);     cudaGetSymbolAddress((void**)&nL, g_nL);
    cudaGetSymbolAddress((void**)&qH, g_qH);     cudaGetSymbolAddress((void**)&qL, g_qL);
    cudaGetSymbolAddress((void**)&kH, g_kH);     cudaGetSymbolAddress((void**)&kL, g_kL);
    cudaGetSymbolAddress((void**)&v, g_v);
    cudaGetSymbolAddress((void**)&vTH, g_vTH);   cudaGetSymbolAddress((void**)&vTL, g_vTL);
    cudaGetSymbolAddress((void**)&ctxH, g_ctxH); cudaGetSymbolAddress((void**)&ctxL, g_ctxL);
    cudaGetSymbolAddress((void**)&h2, g_h2);
    cudaGetSymbolAddress((void**)&x1, g_x1);
    cudaGetSymbolAddress((void**)&x1H, g_x1H);   cudaGetSymbolAddress((void**)&x1L, g_x1L);
    cudaGetSymbolAddress((void**)&gH, g_gH);     cudaGetSymbolAddress((void**)&gL, g_gL);
    cudaGetSymbolAddress((void**)&wH, g_wH);     cudaGetSymbolAddress((void**)&wL, g_wL);
    cudaGetSymbolAddress((void**)&pH, g_pH);     cudaGetSymbolAddress((void**)&pL, g_pL);
    cudaGetSymbolAddress((void**)&energy, g_energy);

    cudaFuncSetAttribute(gemm_bf16s, cudaFuncAttributeMaxDynamicSharedMemorySize, GEMM_SMEM);

    const float inv_sqrt_hd = 0.08838834764831845f;
    const long DSQ = (long)DD * DD;
    __nv_bfloat16 *WqH = wH + 0*DSQ, *WqL = wL + 0*DSQ;
    __nv_bfloat16 *WkH = wH + 1*DSQ, *WkL = wL + 1*DSQ;
    __nv_bfloat16 *WvH = wH + 2*DSQ, *WvL = wL + 2*DSQ;
    __nv_bfloat16 *WoH = wH + 3*DSQ, *WoL = wL + 3*DSQ;
    __nv_bfloat16 *W1H = wH + 4*DSQ, *W1L = wL + 4*DSQ;
    __nv_bfloat16 *W2H = wH + 5*DSQ, *W2L = wL + 5*DSQ;
    __nv_bfloat16 *W3H = wH + 6*DSQ, *W3L = wL + 6*DSQ;

    // 0. transpose + split weights
    dim3 tgridW(DD / 32, DD / 32, 1);
    transpose_split<<<tgridW, 256>>>(Wq, WqH, WqL, DD, DD, 0, 0, 0, 0, 1);
    transpose_split<<<tgridW, 256>>>(Wk, WkH, WkL, DD, DD, 0, 0, 0, 0, 1);
    transpose_split<<<tgridW, 256>>>(Wv, WvH, WvL, DD, DD, 0, 0, 0, 0, 1);
    transpose_split<<<tgridW, 256>>>(Wo, WoH, WoL, DD, DD, 0, 0, 0, 0, 1);
    transpose_split<<<tgridW, 256>>>(W1, W1H, W1L, DD, DD, 0, 0, 0, 0, 1);
    transpose_split<<<tgridW, 256>>>(W2, W2H, W2L, DD, DD, 0, 0, 0, 0, 1);
    transpose_split<<<tgridW, 256>>>(W3, W3H, W3L, DD, DD, 0, 0, 0, 0, 1);

    dim3 gridDense(DD / GBN, MM / GBM, 1);
    dim3 gridQK(TT / GBN, TT / GBM, BB * NHH);
    dim3 gridAV(1, TT / GBM, BB * NHH);

    // 1. norm1
    rmsnorm_split<<<MM, 256>>>(x, scale1, nH, nL);

    // 2. q/k/v projections
    gemm_bf16s<<<gridDense, GTHREADS, GEMM_SMEM>>>(nH, nL, WqH, WqL, bq, nullptr,
        nullptr, qH, qL, DD, DD, DD, DD, 0,0,0,0,0,0, 1, 1.0f, EPI_SPLIT);
    gemm_bf16s<<<gridDense, GTHREADS, GEMM_SMEM>>>(nH, nL, WkH, WkL, bk, nullptr,
        nullptr, kH, kL, DD, DD, DD, DD, 0,0,0,0,0,0, 1, 1.0f, EPI_SPLIT);
    gemm_bf16s<<<gridDense, GTHREADS, GEMM_SMEM>>>(nH, nL, WvH, WvL, bv, nullptr,
        v, nullptr, nullptr, DD, DD, DD, DD, 0,0,0,0,0,0, 1, 1.0f, EPI_C);

    // 3. vT split: [b,h,d,t]
    dim3 tgridV(HDD / 32, TT / 32, BB * NHH);
    transpose_split<<<tgridV, 256>>>(v, vTH, vTL, DD, TT,
        (long)TT * DD, (long)HDD,
        (long)NHH * HDD * TT, (long)HDD * TT, NHH);

    // 4. energy = Q K^T / sqrt(HD)
    gemm_bf16s<<<gridQK, GTHREADS, GEMM_SMEM>>>(qH, qL, kH, kL, nullptr, nullptr,
        energy, nullptr, nullptr,
        HDD, DD, DD, TT,
        (long)TT * DD, (long)HDD,
        (long)TT * DD, (long)HDD,
        (long)NHH * TT * TT, (long)TT * TT,
        NHH, inv_sqrt_hd, EPI_C);

    // 5. softmax -> split probs
    softmax_split<<<BB * NHH * TT, 256>>>(energy, pH, pL);

    // 6. ctx = P @ V
    gemm_bf16s<<<gridAV, GTHREADS, GEMM_SMEM>>>(pH, pL, vTH, vTL, nullptr, nullptr,
        nullptr, ctxH, ctxL,
        TT, TT, TT, DD,
        (long)NHH * TT * TT, (long)TT * TT,
        (long)NHH * HDD * TT, (long)HDD * TT,
        (long)TT * DD, (long)HDD,
        NHH, 1.0f, EPI_SPLIT);

    // 7. h2 = ctx @ Wo + bo + x
    gemm_bf16s<<<gridDense, GTHREADS, GEMM_SMEM>>>(ctxH, ctxL, WoH, WoL, bo, x,
        h2, nullptr, nullptr, DD, DD, DD, DD, 0,0,0,0,0,0, 1, 1.0f, EPI_C);

    // 8. norm2
    rmsnorm_split<<<MM, 256>>>(h2, scale2, nH, nL);

    // 9. x1 = norm @ W1  (fp32 + split)
    gemm_bf16s<<<gridDense, GTHREADS, GEMM_SMEM>>>(nH, nL, W1H, W1L, nullptr, nullptr,
        x1, x1H, x1L, DD, DD, DD, DD, 0,0,0,0,0,0, 1, 1.0f, EPI_C | EPI_SPLIT);

    // 10+11. x2 = x1 @ W2, fused swiglu: g = x1*sigmoid(x1)*x2 -> split
    gemm_bf16s<<<gridDense, GTHREADS, GEMM_SMEM>>>(x1H, x1L, W2H, W2L, nullptr, x1,
        nullptr, gH, gL, DD, DD, DD, DD, 0,0,0,0,0,0, 1, 1.0f, EPI_SWIGLU | EPI_SPLIT);

    // 12. out = g @ W3 + x
    gemm_bf16s<<<gridDense, GTHREADS, GEMM_SMEM>>>(gH, gL, W3H, W3L, nullptr, x,
        out, nullptr, nullptr, DD, DD, DD, DD, 0,0,0,0,0,0, 1, 1.0f, EPI_C);
}